// round 1
// baseline (speedup 1.0000x reference)
#include <cuda_runtime.h>
#include <math.h>

#define LROW 8192
#define NROWS 256
#define NC 64

// Scratch (static device globals; no runtime allocation)
static __device__ float g_h1[(size_t)NROWS * NC * LROW];   // [row][ci][pos]
static __device__ float g_h2[(size_t)NROWS * NC * LROW];   // [row][ci][pos]
static __device__ float g_stat[NROWS * 2];                 // mn, inv_scale per row

// ---------------- f32x2 helpers (Blackwell packed fp32) ----------------
__device__ __forceinline__ unsigned long long dup2(float w) {
    unsigned long long r;
    asm("mov.b64 %0, {%1, %1};" : "=l"(r) : "r"(__float_as_uint(w)));
    return r;
}
__device__ __forceinline__ void ffma2(unsigned long long& d, unsigned long long a, unsigned long long b) {
    asm("fma.rn.f32x2 %0, %1, %2, %0;" : "+l"(d) : "l"(a), "l"(b));
}
__device__ __forceinline__ float2 up2(unsigned long long v) {
    float2 r;
    asm("mov.b64 {%0, %1}, %2;" : "=f"(r.x), "=f"(r.y) : "l"(v));
    return r;
}

// ---------------- K0: per-row min/max -> (mn, 1/max(scale,1e-4)) ----------------
__global__ void k_stats(const float* __restrict__ prim) {
    int row = blockIdx.x, tid = threadIdx.x;
    const float4* p4 = reinterpret_cast<const float4*>(prim + (size_t)row * LROW);
    float mn = 3.4e38f, mx = -3.4e38f;
    for (int i = tid; i < LROW / 4; i += 256) {
        float4 v = p4[i];
        mn = fminf(mn, fminf(fminf(v.x, v.y), fminf(v.z, v.w)));
        mx = fmaxf(mx, fmaxf(fmaxf(v.x, v.y), fmaxf(v.z, v.w)));
    }
    for (int o = 16; o; o >>= 1) {
        mn = fminf(mn, __shfl_xor_sync(0xffffffffu, mn, o));
        mx = fmaxf(mx, __shfl_xor_sync(0xffffffffu, mx, o));
    }
    __shared__ float smn[8], smx[8];
    if ((tid & 31) == 0) { smn[tid >> 5] = mn; smx[tid >> 5] = mx; }
    __syncthreads();
    if (tid == 0) {
        for (int w = 1; w < 8; w++) { mn = fminf(mn, smn[w]); mx = fmaxf(mx, smx[w]); }
        g_stat[2 * row]     = mn;
        g_stat[2 * row + 1] = 1.0f / fmaxf((mx - mn) * 0.5f, 1e-4f);
    }
}

// ---------------- K1: rescale + conv1(K=5,1->64) + tanh ----------------
__global__ void k_conv1(const float* __restrict__ prim,
                        const float* __restrict__ W1,
                        const float* __restrict__ b1) {
    __shared__ float sy[260];
    __shared__ float sw[320];
    __shared__ float sb[64];
    int tid = threadIdx.x;
    int row = blockIdx.y;
    int t0  = blockIdx.x * 256;
    float mn = g_stat[2 * row], inv = g_stat[2 * row + 1];
    const float* pr = prim + (size_t)row * LROW;
    for (int i = tid; i < 260; i += 256) {
        int pos = (t0 - 2 + i) & (LROW - 1);
        sy[i] = (pr[pos] - mn) * inv - 1.0f;
    }
    for (int i = tid; i < 320; i += 256) sw[i] = W1[i];   // [k][c] : k*64+c
    if (tid < 64) sb[tid] = b1[tid];
    __syncthreads();

    float y0 = sy[tid], y1 = sy[tid + 1], y2 = sy[tid + 2], y3 = sy[tid + 3], y4 = sy[tid + 4];
    size_t base = ((size_t)row * NC) * LROW + (t0 + tid);
#pragma unroll 4
    for (int c = 0; c < 64; c++) {
        float a = sb[c] + y0 * sw[c] + y1 * sw[64 + c] + y2 * sw[128 + c]
                        + y3 * sw[192 + c] + y4 * sw[256 + c];
        g_h1[base + (size_t)c * LROW] = tanhf(a);
    }
}

// ---------------- K2: conv2(K=5,64->64) + tanh  (fma.f32x2 register-tiled) ----------------
// Tile: 128 points/block, 256 threads. Thread owns 8 points x 4 out-channels.
// hs0[ci][j] = h1[t0-2+j]; hs1[ci][j] = hs0[ci][j+1] (shifted copy -> aligned f32x2 for odd shifts)
__global__ void __launch_bounds__(256, 2) k_conv2(const float* __restrict__ W2,
                                                  const float* __restrict__ b2) {
    extern __shared__ float dynsm[];
    float* hs0 = dynsm;               // 64 x 136
    float* hs1 = dynsm + 64 * 136;    // 64 x 136
    int tid = threadIdx.x;
    int row = blockIdx.y;
    int t0  = blockIdx.x * 128;

    for (int li = tid; li < 64 * 132; li += 256) {
        int ci = li / 132;
        int j  = li - ci * 132;
        float v = g_h1[(((size_t)row * 64 + ci) << 13) + ((t0 - 2 + j) & (LROW - 1))];
        hs0[ci * 136 + j] = v;
        if (j) hs1[ci * 136 + j - 1] = v;
    }
    __syncthreads();

    int p0  = (tid >> 4) << 3;   // 0..120 step 8
    int co0 = (tid & 15) << 2;   // 0..60 step 4

    unsigned long long acc[4][4];
#pragma unroll
    for (int pp = 0; pp < 4; pp++)
#pragma unroll
        for (int c = 0; c < 4; c++) acc[pp][c] = 0ULL;

#pragma unroll
    for (int k = 0; k < 5; k++) {
        // even shifts from hs0, odd shifts from hs1 (all pair-aligned)
        const float* hbase = ((k & 1) ? hs1 : hs0) + ((k & 1) ? (p0 + k - 1) : (p0 + k));
        const float4* wb = reinterpret_cast<const float4*>(W2 + k * 4096 + co0);
#pragma unroll 2
        for (int ci = 0; ci < 64; ci++) {
            float4 w = __ldg(wb + ci * 16);
            unsigned long long w0 = dup2(w.x), w1 = dup2(w.y), w2d = dup2(w.z), w3d = dup2(w.w);
            const float* h = hbase + ci * 136;
            unsigned long long h0 = *reinterpret_cast<const unsigned long long*>(h);
            unsigned long long h1 = *reinterpret_cast<const unsigned long long*>(h + 2);
            unsigned long long h2 = *reinterpret_cast<const unsigned long long*>(h + 4);
            unsigned long long h3 = *reinterpret_cast<const unsigned long long*>(h + 6);
            ffma2(acc[0][0], h0, w0); ffma2(acc[0][1], h0, w1); ffma2(acc[0][2], h0, w2d); ffma2(acc[0][3], h0, w3d);
            ffma2(acc[1][0], h1, w0); ffma2(acc[1][1], h1, w1); ffma2(acc[1][2], h1, w2d); ffma2(acc[1][3], h1, w3d);
            ffma2(acc[2][0], h2, w0); ffma2(acc[2][1], h2, w1); ffma2(acc[2][2], h2, w2d); ffma2(acc[2][3], h2, w3d);
            ffma2(acc[3][0], h3, w0); ffma2(acc[3][1], h3, w1); ffma2(acc[3][2], h3, w2d); ffma2(acc[3][3], h3, w3d);
        }
    }

    size_t obase = (((size_t)row * 64) << 13) + (size_t)(t0 + p0);
#pragma unroll
    for (int c = 0; c < 4; c++) {
        float b = __ldg(b2 + co0 + c);
        size_t ob = obase + ((size_t)(co0 + c) << 13);
#pragma unroll
        for (int pp = 0; pp < 4; pp++) {
            float2 r = up2(acc[pp][c]);
            g_h2[ob + 2 * pp]     = tanhf(r.x + b);
            g_h2[ob + 2 * pp + 1] = tanhf(r.y + b);
        }
    }
}

// ---------------- K3: conv3 + null-space alpha + grad + TVD flux + update ----------------
// TILE=253 output points; 256 threads compute exactly 256 grad points [-2, 253].
__global__ void __launch_bounds__(256, 2) k_out(const float* __restrict__ prim,
                                                const float* __restrict__ W3,
                                                const float* __restrict__ b3,
                                                float* __restrict__ out) {
    extern __shared__ float dynsm[];
    float* sh2 = dynsm;               // 64 x 260
    float* sp  = dynsm + 64 * 260;    // 260  Prim[t0-4 .. t0+255]
    float* sg  = sp + 260;            // 256  grad at global offset (t-2)
    float* sf  = sg + 256;            // 254  flux at global offset (t-1)
    int tid = threadIdx.x;
    int row = blockIdx.y;
    int t0  = blockIdx.x * 253;
    size_t rb = (size_t)row * LROW;

    for (int li = tid; li < 64 * 260; li += 256) {
        int ci = li / 260;
        int j  = li - ci * 260;
        sh2[ci * 260 + j] = g_h2[(((size_t)row * 64 + ci) << 13) + ((t0 - 4 + j) & (LROW - 1))];
    }
    for (int j = tid; j < 260; j += 256) sp[j] = prim[rb + ((t0 - 4 + j) & (LROW - 1))];
    __syncthreads();

    {   // conv3 -> coeffs -> alpha -> grad, one point per thread (g = t-2)
        int t = tid;
        float c0 = __ldg(b3 + 0), c1 = __ldg(b3 + 1), c2 = __ldg(b3 + 2), c3 = __ldg(b3 + 3);
#pragma unroll
        for (int k = 0; k < 5; k++) {
            const float4* wb = reinterpret_cast<const float4*>(W3 + k * 256);
            const float* h = sh2 + (t + k);
#pragma unroll 4
            for (int ci = 0; ci < 64; ci++) {
                float hv = h[ci * 260];
                float4 w = __ldg(wb + ci);
                c0 += hv * w.x; c1 += hv * w.y; c2 += hv * w.z; c3 += hv * w.w;
            }
        }
        float S = c0 + c1 + c2 + c3;
        // NULL_BASIS rows (LAPACK dgesdd of [[1,1,1,1,1]]): col0 = -1/sqrt(5),
        // diag = 1 - 1/(5+sqrt5), off = -1/(5+sqrt5)  ->  alpha collapses to:
        const float NB0 = -0.44721359549995793f;
        const float NBD = -0.13819660112501052f;
        float a0 = (float)(1.0 / 12.0) + NB0 * S;
        float a1 = (float)(-2.0 / 3.0) + c0 + NBD * S;
        float a2 =                        c1 + NBD * S;
        float a3 = (float)( 2.0 / 3.0) + c2 + NBD * S;
        float a4 = (float)(-1.0 / 12.0) + c3 + NBD * S;
        // patches: Prim[g+k-2] -> sp[t+k]
        float g = sp[t] * a0 + sp[t + 1] * a1 + sp[t + 2] * a2 + sp[t + 3] * a3 + sp[t + 4] * a4;
        sg[t] = g * 64.0f;   // / DX
    }
    __syncthreads();

    if (tid < 254) {   // flux at f = t-1 ; grad(m) lives at sg[m+2]
        int t = tid;
        float gm1 = sg[t], g0 = sg[t + 1], g1 = sg[t + 2];
        float aa0 = (g0 < 0.0f) ? -1.0f : 1.0f;
        float ri0 = gm1 / (fmaxf(fabsf(g0), 1e-15f) * aa0);
        float phi0 = (ri0 * ri0 + ri0) / (ri0 * ri0 + 1.0f);
        float aa1 = (g1 < 0.0f) ? -1.0f : 1.0f;
        float ri1 = g0 / (fmaxf(fabsf(g1), 1e-15f) * aa1);
        float phi1 = (ri1 * ri1 + ri1) / (ri1 * ri1 + 1.0f);
        float uL = sp[t + 3] + 0.0078125f * phi0 * g0;   // 0.5*DX = 1/128
        float uR = sp[t + 4] - 0.0078125f * phi1 * g1;
        sf[t] = 0.25f * (uL * uL + uR * uR) - 0.25f * fabsf(uL + uR) * (uR - uL);
    }
    __syncthreads();

    if (tid < 253) {
        int o = t0 + tid;
        if (o < LROW)
            out[rb + o] = sp[tid + 4] - 0.01f * (sf[tid + 1] - sf[tid]);
    }
}

// ---------------- launch ----------------
extern "C" void kernel_launch(void* const* d_in, const int* in_sizes, int n_in,
                              void* d_out, int out_size) {
    const float* Prim = (const float*)d_in[0];
    const float* W1   = (const float*)d_in[1];
    const float* b1   = (const float*)d_in[2];
    const float* W2   = (const float*)d_in[3];
    const float* b2   = (const float*)d_in[4];
    const float* W3   = (const float*)d_in[5];
    const float* b3   = (const float*)d_in[6];
    float* out = (float*)d_out;

    cudaFuncSetAttribute(k_conv2, cudaFuncAttributeMaxDynamicSharedMemorySize, 2 * 64 * 136 * 4);
    cudaFuncSetAttribute(k_out,   cudaFuncAttributeMaxDynamicSharedMemorySize, (64 * 260 + 260 + 256 + 254) * 4);

    k_stats<<<NROWS, 256>>>(Prim);
    k_conv1<<<dim3(LROW / 256, NROWS), 256>>>(Prim, W1, b1);
    k_conv2<<<dim3(LROW / 128, NROWS), 256, 2 * 64 * 136 * 4>>>(W2, b2);
    k_out<<<dim3((LROW + 252) / 253, NROWS), 256, (64 * 260 + 260 + 256 + 254) * 4>>>(Prim, W3, b3, out);
}

// round 3
// speedup vs baseline: 7.7717x; 7.7717x over previous
#include <cuda_runtime.h>
#include <cuda_bf16.h>
#include <cstdint>

#define LROW 8192
#define NROWS 256
#define OUT_TILE 249
#define NTILES 33   // 33*249 = 8217 >= 8192

// ---------------- device globals ----------------
static __device__ uint32_t g_w2f[20 * 8 * 32 * 2];  // conv2 weights, B-fragment order
static __device__ uint32_t g_w3f[20 * 32 * 2];      // conv3 weights, B-fragment order
static __device__ float    g_stat[NROWS * 2];

// ---------------- smem layout (bytes) ----------------
#define OFF_H    0                    // sH1/sH2 overlay: 260 rows x 144B (72 bf16 stride)
#define OFF_W2F  37440                // 40960
#define OFF_W3F  (OFF_W2F + 40960)    // 78400: 5120
#define OFF_PRIM (OFF_W3F + 5120)     // 83520: 264 f32
#define OFF_Y    (OFF_PRIM + 1056)    // 84576: 264 f32
#define OFF_W1   (OFF_Y + 1056)       // 85632: 320 f32
#define OFF_B1   (OFF_W1 + 1280)      // 86912: 64 f32
#define OFF_B2   (OFF_B1 + 256)       // 87168: 64 f32
#define OFF_B3   (OFF_B2 + 256)       // 87424: 4 f32 (pad 32)
#define OFF_COEF (OFF_B3 + 32)        // 87456: 256 x float4
#define OFF_G    (OFF_COEF + 4096)    // 91552: 252 f32 (pad 1024)
#define OFF_F    (OFF_G + 1024)       // 92576: 250 f32 (pad 1024)
#define SMEM_TOTAL (OFF_F + 1024)     // 93600

// ---------------- helpers ----------------
__device__ __forceinline__ uint32_t smem_u32(const void* p) {
    uint32_t a;
    asm("{ .reg .u64 t; cvta.to.shared.u64 t, %1; cvt.u32.u64 %0, t; }" : "=r"(a) : "l"(p));
    return a;
}
__device__ __forceinline__ void sts32(uint32_t a, uint32_t v) {
    asm volatile("st.shared.b32 [%0], %1;" :: "r"(a), "r"(v) : "memory");
}
__device__ __forceinline__ void ldmatrix_x4(uint32_t* r, uint32_t a) {
    asm volatile("ldmatrix.sync.aligned.m8n8.x4.shared.b16 {%0,%1,%2,%3}, [%4];"
                 : "=r"(r[0]), "=r"(r[1]), "=r"(r[2]), "=r"(r[3]) : "r"(a));
}
__device__ __forceinline__ void mma_bf16(float* d, const uint32_t* a, uint32_t b0, uint32_t b1) {
    asm volatile("mma.sync.aligned.m16n8k16.row.col.f32.bf16.bf16.f32 "
                 "{%0,%1,%2,%3}, {%4,%5,%6,%7}, {%8,%9}, {%0,%1,%2,%3};"
                 : "+f"(d[0]), "+f"(d[1]), "+f"(d[2]), "+f"(d[3])
                 : "r"(a[0]), "r"(a[1]), "r"(a[2]), "r"(a[3]), "r"(b0), "r"(b1));
}
__device__ __forceinline__ float tanh_ap(float x) {
    float r;
    asm("tanh.approx.f32 %0, %1;" : "=f"(r) : "f"(x));
    return r;
}
__device__ __forceinline__ uint32_t pack_bf16(float lo, float hi) {
    uint32_t u;
    asm("cvt.rn.bf16x2.f32 %0, %1, %2;" : "=r"(u) : "f"(hi), "f"(lo));
    return u;
}

// ---------------- K0: per-row min/max ----------------
__global__ void k_stats(const float* __restrict__ prim) {
    int row = blockIdx.x, tid = threadIdx.x;
    const float4* p4 = reinterpret_cast<const float4*>(prim + (size_t)row * LROW);
    float mn = 3.4e38f, mx = -3.4e38f;
    for (int i = tid; i < LROW / 4; i += 256) {
        float4 v = p4[i];
        mn = fminf(mn, fminf(fminf(v.x, v.y), fminf(v.z, v.w)));
        mx = fmaxf(mx, fmaxf(fmaxf(v.x, v.y), fmaxf(v.z, v.w)));
    }
    for (int o = 16; o; o >>= 1) {
        mn = fminf(mn, __shfl_xor_sync(0xffffffffu, mn, o));
        mx = fmaxf(mx, __shfl_xor_sync(0xffffffffu, mx, o));
    }
    __shared__ float smn[8], smx[8];
    if ((tid & 31) == 0) { smn[tid >> 5] = mn; smx[tid >> 5] = mx; }
    __syncthreads();
    if (tid == 0) {
        for (int w = 1; w < 8; w++) { mn = fminf(mn, smn[w]); mx = fmaxf(mx, smx[w]); }
        g_stat[2 * row]     = mn;
        g_stat[2 * row + 1] = 1.0f / fmaxf((mx - mn) * 0.5f, 1e-4f);
    }
}

// ---------------- prep: pack weights into mma B-fragment order ----------------
// B frag (m16n8k16): lane holds B[k=(lane%4)*2 + r*8 + {0,1}][n=lane/4] in reg r.
// K index = kshift*64 + ci ; kb = kshift*4 + ci16chunk.
__global__ void k_prep(const float* __restrict__ W2, const float* __restrict__ W3) {
    int tid = threadIdx.x;
    for (int i = tid; i < 20 * 8 * 32 * 2; i += 256) {
        int r = i & 1, lane = (i >> 1) & 31, nb = (i >> 6) & 7, kb = i >> 9;
        int tg = lane & 3, gg = lane >> 2;
        int k = kb >> 2;
        int ci0 = (kb & 3) * 16 + tg * 2 + r * 8;
        int co = nb * 8 + gg;
        float v0 = W2[k * 4096 + ci0 * 64 + co];
        float v1 = W2[k * 4096 + (ci0 + 1) * 64 + co];
        g_w2f[i] = pack_bf16(v0, v1);
    }
    for (int i = tid; i < 20 * 32 * 2; i += 256) {
        int r = i & 1, lane = (i >> 1) & 31, kb = i >> 6;
        int tg = lane & 3, gg = lane >> 2;
        int k = kb >> 2;
        int ci0 = (kb & 3) * 16 + tg * 2 + r * 8;
        float v0 = (gg < 4) ? W3[k * 256 + ci0 * 4 + gg] : 0.0f;
        float v1 = (gg < 4) ? W3[k * 256 + (ci0 + 1) * 4 + gg] : 0.0f;
        g_w3f[i] = pack_bf16(v0, v1);
    }
}

// ---------------- mega kernel ----------------
__global__ void __launch_bounds__(256, 2)
k_mega(const float* __restrict__ prim,
       const float* __restrict__ W1g, const float* __restrict__ b1g,
       const float* __restrict__ b2g, const float* __restrict__ b3g,
       float* __restrict__ out) {
    extern __shared__ __align__(16) char smem[];
    int tid = threadIdx.x;
    int w = tid >> 5, lane = tid & 31;
    int row = blockIdx.y;
    int t0 = blockIdx.x * OUT_TILE;
    size_t rb = (size_t)row * LROW;

    uint32_t sh_base = smem_u32(smem) + OFF_H;
    float* sPrim = reinterpret_cast<float*>(smem + OFF_PRIM);
    float* sy    = reinterpret_cast<float*>(smem + OFF_Y);
    float* sw1   = reinterpret_cast<float*>(smem + OFF_W1);
    float* sb1   = reinterpret_cast<float*>(smem + OFF_B1);
    float* sb2   = reinterpret_cast<float*>(smem + OFF_B2);
    float* sb3   = reinterpret_cast<float*>(smem + OFF_B3);
    float* scoef = reinterpret_cast<float*>(smem + OFF_COEF);
    float* sg    = reinterpret_cast<float*>(smem + OFF_G);
    float* sf    = reinterpret_cast<float*>(smem + OFF_F);

    // ---- phase 0: load weights/fragments + prim + rescale ----
    {
        uint4* d2 = reinterpret_cast<uint4*>(smem + OFF_W2F);
        const uint4* s2 = reinterpret_cast<const uint4*>(g_w2f);
        for (int i = tid; i < 2560; i += 256) d2[i] = s2[i];
        uint4* d3 = reinterpret_cast<uint4*>(smem + OFF_W3F);
        const uint4* s3 = reinterpret_cast<const uint4*>(g_w3f);
        for (int i = tid; i < 320; i += 256) d3[i] = s3[i];
        float mn = g_stat[2 * row], inv = g_stat[2 * row + 1];
        for (int j = tid; j < 264; j += 256) {
            float p = prim[rb + ((t0 - 8 + j) & (LROW - 1))];
            sPrim[j] = p;
            sy[j] = (p - mn) * inv - 1.0f;
        }
        for (int i = tid; i < 320; i += 256) sw1[i] = W1g[i];
        if (tid < 64) sb1[tid] = b1g[tid];
        if (tid < 64) sb2[tid] = b2g[tid];
        if (tid < 4)  sb3[tid] = b3g[tid];
    }
    __syncthreads();

    // ---- phase 1: conv1 + tanh -> sH1 (260 rows x 64 ch bf16, 144B stride) ----
    for (int j = tid; j < 260; j += 256) {
        float y0 = sy[j], y1 = sy[j + 1], y2 = sy[j + 2], y3 = sy[j + 3], y4 = sy[j + 4];
        uint32_t addr = sh_base + j * 144;
#pragma unroll 8
        for (int cp = 0; cp < 32; cp++) {
            int c0 = 2 * cp, c1 = 2 * cp + 1;
            float a0 = sb1[c0] + y0 * sw1[c0] + y1 * sw1[64 + c0] + y2 * sw1[128 + c0]
                               + y3 * sw1[192 + c0] + y4 * sw1[256 + c0];
            float a1 = sb1[c1] + y0 * sw1[c1] + y1 * sw1[64 + c1] + y2 * sw1[128 + c1]
                               + y3 * sw1[192 + c1] + y4 * sw1[256 + c1];
            sts32(addr + cp * 4, pack_bf16(tanh_ap(a0), tanh_ap(a1)));
        }
    }
    __syncthreads();

    // ---- phase 2: conv2 MMA (M=256, N=64, K=320), warp w owns rows m0..m0+31 ----
    int m0 = w * 32;
    float acc[2][8][4];
#pragma unroll
    for (int mt = 0; mt < 2; mt++)
#pragma unroll
        for (int nb = 0; nb < 8; nb++)
#pragma unroll
            for (int q = 0; q < 4; q++) acc[mt][nb][q] = 0.0f;

#pragma unroll 5
    for (int kb = 0; kb < 20; kb++) {
        int kk = kb >> 2;
        uint32_t colb = (uint32_t)(((kb & 3) * 16 + (lane >> 4) * 8) * 2);
        uint32_t a[2][4];
#pragma unroll
        for (int mt = 0; mt < 2; mt++) {
            uint32_t r = (uint32_t)(m0 + mt * 16 + (lane & 15) + kk);
            ldmatrix_x4(a[mt], sh_base + r * 144 + colb);
        }
#pragma unroll
        for (int nb = 0; nb < 8; nb++) {
            uint2 b = *reinterpret_cast<const uint2*>(
                smem + OFF_W2F + ((((kb << 3) + nb) << 5) + lane) * 8);
            mma_bf16(acc[0][nb], a[0], b.x, b.y);
            mma_bf16(acc[1][nb], a[1], b.x, b.y);
        }
    }

    // ---- phase 3: tanh epilogue -> sH2 (overlays sH1) ----
    int tg = lane & 3, gg = lane >> 2;
    uint32_t h2p[2][8][2];
#pragma unroll
    for (int mt = 0; mt < 2; mt++)
#pragma unroll
        for (int nb = 0; nb < 8; nb++) {
            int c0 = nb * 8 + tg * 2;
            float b0 = sb2[c0], b1v = sb2[c0 + 1];
            h2p[mt][nb][0] = pack_bf16(tanh_ap(acc[mt][nb][0] + b0),
                                       tanh_ap(acc[mt][nb][1] + b1v));
            h2p[mt][nb][1] = pack_bf16(tanh_ap(acc[mt][nb][2] + b0),
                                       tanh_ap(acc[mt][nb][3] + b1v));
        }
    __syncthreads();   // all warps done reading sH1
#pragma unroll
    for (int mt = 0; mt < 2; mt++)
#pragma unroll
        for (int nb = 0; nb < 8; nb++) {
            uint32_t r0 = (uint32_t)(m0 + mt * 16 + gg);
            uint32_t cb = (uint32_t)((nb * 8 + tg * 2) * 2);
            sts32(sh_base + r0 * 144 + cb, h2p[mt][nb][0]);
            sts32(sh_base + (r0 + 8) * 144 + cb, h2p[mt][nb][1]);
        }
    __syncthreads();

    // ---- phase 4: conv3 MMA (M=256, N=8, K=320) -> coeffs ----
    float acc3[2][4];
#pragma unroll
    for (int mt = 0; mt < 2; mt++)
#pragma unroll
        for (int q = 0; q < 4; q++) acc3[mt][q] = 0.0f;
#pragma unroll 5
    for (int kb = 0; kb < 20; kb++) {
        int kk = kb >> 2;
        uint32_t colb = (uint32_t)(((kb & 3) * 16 + (lane >> 4) * 8) * 2);
        uint32_t a[2][4];
#pragma unroll
        for (int mt = 0; mt < 2; mt++) {
            uint32_t r = (uint32_t)(m0 + mt * 16 + (lane & 15) + kk);
            ldmatrix_x4(a[mt], sh_base + r * 144 + colb);
        }
        uint2 b = *reinterpret_cast<const uint2*>(
            smem + OFF_W3F + (((kb << 5) + lane)) * 8);
        mma_bf16(acc3[0], a[0], b.x, b.y);
        mma_bf16(acc3[1], a[1], b.x, b.y);
    }
    if (tg < 2) {
#pragma unroll
        for (int mt = 0; mt < 2; mt++) {
            int p = m0 + mt * 16 + gg;
            int c0 = tg * 2;
            scoef[p * 4 + c0]           = acc3[mt][0] + sb3[c0];
            scoef[p * 4 + c0 + 1]       = acc3[mt][1] + sb3[c0 + 1];
            scoef[(p + 8) * 4 + c0]     = acc3[mt][2] + sb3[c0];
            scoef[(p + 8) * 4 + c0 + 1] = acc3[mt][3] + sb3[c0 + 1];
        }
    }
    __syncthreads();

    // ---- phase 5: alpha -> grad -> TVD flux -> update ----
    if (tid < 252) {   // grad at position t0-2+tid
        float4 c = *reinterpret_cast<const float4*>(scoef + tid * 4);
        float S = c.x + c.y + c.z + c.w;
        const float NB0 = -0.44721359549995793f;
        const float NBD = -0.13819660112501052f;
        float a0 = (float)( 1.0 / 12.0) + NB0 * S;
        float a1 = (float)(-2.0 / 3.0)  + c.x + NBD * S;
        float a2 =                        c.y + NBD * S;
        float a3 = (float)( 2.0 / 3.0)  + c.z + NBD * S;
        float a4 = (float)(-1.0 / 12.0) + c.w + NBD * S;
        float g = sPrim[tid + 4] * a0 + sPrim[tid + 5] * a1 + sPrim[tid + 6] * a2
                + sPrim[tid + 7] * a3 + sPrim[tid + 8] * a4;
        sg[tid] = g * 64.0f;
    }
    __syncthreads();
    if (tid < 250) {   // flux at position t0-1+tid
        float gm1 = sg[tid], g0 = sg[tid + 1], g1 = sg[tid + 2];
        float aa0 = (g0 < 0.0f) ? -1.0f : 1.0f;
        float ri0 = gm1 / (fmaxf(fabsf(g0), 1e-15f) * aa0);
        float phi0 = (ri0 * ri0 + ri0) / (ri0 * ri0 + 1.0f);
        float aa1 = (g1 < 0.0f) ? -1.0f : 1.0f;
        float ri1 = g0 / (fmaxf(fabsf(g1), 1e-15f) * aa1);
        float phi1 = (ri1 * ri1 + ri1) / (ri1 * ri1 + 1.0f);
        float uL = sPrim[tid + 7] + 0.0078125f * phi0 * g0;
        float uR = sPrim[tid + 8] - 0.0078125f * phi1 * g1;
        sf[tid] = 0.25f * (uL * uL + uR * uR) - 0.25f * fabsf(uL + uR) * (uR - uL);
    }
    __syncthreads();
    if (tid < OUT_TILE) {
        int o = t0 + tid;
        if (o < LROW)
            out[rb + o] = sPrim[tid + 8] - 0.01f * (sf[tid + 1] - sf[tid]);
    }
}

// ---------------- launch ----------------
extern "C" void kernel_launch(void* const* d_in, const int* in_sizes, int n_in,
                              void* d_out, int out_size) {
    const float* Prim = (const float*)d_in[0];
    const float* W1   = (const float*)d_in[1];
    const float* b1   = (const float*)d_in[2];
    const float* W2   = (const float*)d_in[3];
    const float* b2   = (const float*)d_in[4];
    const float* W3   = (const float*)d_in[5];
    const float* b3   = (const float*)d_in[6];
    float* out = (float*)d_out;

    cudaFuncSetAttribute(k_mega, cudaFuncAttributeMaxDynamicSharedMemorySize, SMEM_TOTAL);

    k_stats<<<NROWS, 256>>>(Prim);
    k_prep<<<1, 256>>>(W2, W3);
    k_mega<<<dim3(NTILES, NROWS), 256, SMEM_TOTAL>>>(Prim, W1, b1, b2, b3, out);
}

// round 4
// speedup vs baseline: 7.8056x; 1.0044x over previous
#include <cuda_runtime.h>
#include <cuda_bf16.h>
#include <cstdint>

#define LROW 8192
#define NROWS 256
#define OUT_TILE 249
#define NTILES 33   // 33*249 = 8217 >= 8192

// ---------------- device globals ----------------
static __device__ uint32_t g_w2f[10 * 8 * 32 * 2];  // conv2 e4m3 B-fragments
static __device__ uint32_t g_w3f[10 * 32 * 2];      // conv3 e4m3 B-fragments
static __device__ float    g_stat[NROWS * 2];

// ---------------- smem layout (bytes) ----------------
// H rows: 260 x 80B (64 e4m3 + 16B pad; stride 80 => conflict-free ldmatrix)
#define OFF_H    0
#define OFF_W2F  20800                 // 10*8*32*8   = 20480
#define OFF_W3F  (OFF_W2F + 20480)    // 41280: 2560
#define OFF_PRIM (OFF_W3F + 2560)     // 43840: 264 f32
#define OFF_Y    (OFF_PRIM + 1056)    // 44896: 264 f32
#define OFF_W1   (OFF_Y + 1056)       // 45952: 320 f32
#define OFF_B1   (OFF_W1 + 1280)      // 47232: 64 f32
#define OFF_B2   (OFF_B1 + 256)       // 47488: 64 f32
#define OFF_B3   (OFF_B2 + 256)       // 47744: 4 f32 (pad 32)
#define OFF_COEF (OFF_B3 + 32)        // 47776: 256 x float4
#define OFF_G    (OFF_COEF + 4096)    // 51872: 252 f32 (pad 1024)
#define OFF_F    (OFF_G + 1024)       // 52896: 250 f32 (pad 1024)
#define SMEM_TOTAL (OFF_F + 1024)     // 53920

// ---------------- helpers ----------------
__device__ __forceinline__ uint32_t smem_u32(const void* p) {
    uint32_t a;
    asm("{ .reg .u64 t; cvta.to.shared.u64 t, %1; cvt.u32.u64 %0, t; }" : "=r"(a) : "l"(p));
    return a;
}
__device__ __forceinline__ void sts32(uint32_t a, uint32_t v) {
    asm volatile("st.shared.b32 [%0], %1;" :: "r"(a), "r"(v) : "memory");
}
__device__ __forceinline__ void sts16(uint32_t a, unsigned short v) {
    asm volatile("st.shared.b16 [%0], %1;" :: "r"(a), "h"(v) : "memory");
}
__device__ __forceinline__ void ldmatrix_x4(uint32_t* r, uint32_t a) {
    asm volatile("ldmatrix.sync.aligned.m8n8.x4.shared.b16 {%0,%1,%2,%3}, [%4];"
                 : "=r"(r[0]), "=r"(r[1]), "=r"(r[2]), "=r"(r[3]) : "r"(a));
}
__device__ __forceinline__ void mma_fp8(float* d, const uint32_t* a, uint32_t b0, uint32_t b1) {
    asm volatile("mma.sync.aligned.m16n8k32.row.col.f32.e4m3.e4m3.f32 "
                 "{%0,%1,%2,%3}, {%4,%5,%6,%7}, {%8,%9}, {%0,%1,%2,%3};"
                 : "+f"(d[0]), "+f"(d[1]), "+f"(d[2]), "+f"(d[3])
                 : "r"(a[0]), "r"(a[1]), "r"(a[2]), "r"(a[3]), "r"(b0), "r"(b1));
}
// tanh of a pair via f16x2, result packed e4m3x2 (byte0 = tanh(x0))
__device__ __forceinline__ unsigned short tanh2_e4m3(float x0, float x1) {
    uint32_t h;
    asm("cvt.rn.f16x2.f32 %0, %1, %2;" : "=r"(h) : "f"(x1), "f"(x0));
    asm("tanh.approx.f16x2 %0, %0;" : "+r"(h));
    unsigned short e;
    asm("cvt.rn.satfinite.e4m3x2.f16x2 %0, %1;" : "=h"(e) : "r"(h));
    return e;
}
__device__ __forceinline__ uint32_t pack4_e4m3(float v0, float v1, float v2, float v3) {
    unsigned short lo, hi;
    asm("cvt.rn.satfinite.e4m3x2.f32 %0, %1, %2;" : "=h"(lo) : "f"(v1), "f"(v0));
    asm("cvt.rn.satfinite.e4m3x2.f32 %0, %1, %2;" : "=h"(hi) : "f"(v3), "f"(v2));
    uint32_t r;
    asm("mov.b32 %0, {%1,%2};" : "=r"(r) : "h"(lo), "h"(hi));
    return r;
}

// ---------------- K0: per-row min/max ----------------
__global__ void k_stats(const float* __restrict__ prim) {
    int row = blockIdx.x, tid = threadIdx.x;
    const float4* p4 = reinterpret_cast<const float4*>(prim + (size_t)row * LROW);
    float mn = 3.4e38f, mx = -3.4e38f;
    for (int i = tid; i < LROW / 4; i += 256) {
        float4 v = p4[i];
        mn = fminf(mn, fminf(fminf(v.x, v.y), fminf(v.z, v.w)));
        mx = fmaxf(mx, fmaxf(fmaxf(v.x, v.y), fmaxf(v.z, v.w)));
    }
    for (int o = 16; o; o >>= 1) {
        mn = fminf(mn, __shfl_xor_sync(0xffffffffu, mn, o));
        mx = fmaxf(mx, __shfl_xor_sync(0xffffffffu, mx, o));
    }
    __shared__ float smn[8], smx[8];
    if ((tid & 31) == 0) { smn[tid >> 5] = mn; smx[tid >> 5] = mx; }
    __syncthreads();
    if (tid == 0) {
        for (int w = 1; w < 8; w++) { mn = fminf(mn, smn[w]); mx = fmaxf(mx, smx[w]); }
        g_stat[2 * row]     = mn;
        g_stat[2 * row + 1] = 1.0f / fmaxf((mx - mn) * 0.5f, 1e-4f);
    }
}

// ---------------- prep: pack weights into fp8 mma B-fragment order ----------------
// m16n8k32 B frag: thread(tg=lane&3, gg=lane>>2): b_r = e4m3x4 of k-rows
// (kchunk-local) r*16 + tg*4 + {0..3}, col gg.  K index = kshift*64 + ci,
// kb = kshift*2 + (ci>=32).
__global__ void k_prep(const float* __restrict__ W2, const float* __restrict__ W3) {
    int tid = blockIdx.x * blockDim.x + threadIdx.x;
    int nth = gridDim.x * blockDim.x;
    for (int i = tid; i < 10 * 8 * 32 * 2; i += nth) {
        int r = i & 1, lane = (i >> 1) & 31, nb = (i >> 6) & 7, kb = i >> 9;
        int tg = lane & 3, gg = lane >> 2;
        int kshift = kb >> 1;
        int ci = (kb & 1) * 32 + r * 16 + tg * 4;
        int co = nb * 8 + gg;
        const float* wb = W2 + kshift * 4096 + ci * 64 + co;
        g_w2f[i] = pack4_e4m3(wb[0], wb[64], wb[128], wb[192]);
    }
    for (int i = tid; i < 10 * 32 * 2; i += nth) {
        int r = i & 1, lane = (i >> 1) & 31, kb = i >> 6;
        int tg = lane & 3, gg = lane >> 2;
        int kshift = kb >> 1;
        int ci = (kb & 1) * 32 + r * 16 + tg * 4;
        float v0 = 0, v1 = 0, v2 = 0, v3 = 0;
        if (gg < 4) {
            const float* wb = W3 + kshift * 256 + ci * 4 + gg;
            v0 = wb[0]; v1 = wb[4]; v2 = wb[8]; v3 = wb[12];
        }
        g_w3f[i] = pack4_e4m3(v0, v1, v2, v3);
    }
}

// ---------------- mega kernel ----------------
__global__ void __launch_bounds__(256, 2)
k_mega(const float* __restrict__ prim,
       const float* __restrict__ W1g, const float* __restrict__ b1g,
       const float* __restrict__ b2g, const float* __restrict__ b3g,
       float* __restrict__ out) {
    extern __shared__ __align__(16) char smem[];
    int tid = threadIdx.x;
    int w = tid >> 5, lane = tid & 31;
    int tg = lane & 3, gg = lane >> 2;
    int row = blockIdx.y;
    int t0 = blockIdx.x * OUT_TILE;
    size_t rb = (size_t)row * LROW;

    uint32_t sh_base = smem_u32(smem) + OFF_H;
    float* sPrim = reinterpret_cast<float*>(smem + OFF_PRIM);
    float* sy    = reinterpret_cast<float*>(smem + OFF_Y);
    float* sw1   = reinterpret_cast<float*>(smem + OFF_W1);
    float* sb1   = reinterpret_cast<float*>(smem + OFF_B1);
    float* sb2   = reinterpret_cast<float*>(smem + OFF_B2);
    float* sb3   = reinterpret_cast<float*>(smem + OFF_B3);
    float* scoef = reinterpret_cast<float*>(smem + OFF_COEF);
    float* sg    = reinterpret_cast<float*>(smem + OFF_G);
    float* sf    = reinterpret_cast<float*>(smem + OFF_F);

    // ---- phase 0: stage weights + prim + rescale ----
    {
        uint4* d2 = reinterpret_cast<uint4*>(smem + OFF_W2F);
        const uint4* s2 = reinterpret_cast<const uint4*>(g_w2f);
        for (int i = tid; i < 1280; i += 256) d2[i] = s2[i];
        uint4* d3 = reinterpret_cast<uint4*>(smem + OFF_W3F);
        const uint4* s3 = reinterpret_cast<const uint4*>(g_w3f);
        for (int i = tid; i < 160; i += 256) d3[i] = s3[i];
        float mn = g_stat[2 * row], inv = g_stat[2 * row + 1];
        for (int j = tid; j < 264; j += 256) {
            float p = prim[rb + ((t0 - 8 + j) & (LROW - 1))];
            sPrim[j] = p;
            sy[j] = (p - mn) * inv - 1.0f;
        }
        for (int i = tid; i < 320; i += 256) sw1[i] = W1g[i];
        if (tid < 64) sb1[tid] = b1g[tid];
        if (tid < 64) sb2[tid] = b2g[tid];
        if (tid < 4)  sb3[tid] = b3g[tid];
    }
    __syncthreads();

    // ---- phase 1: conv1 + tanh -> sH1 (260 rows x 64 e4m3, 80B stride) ----
    for (int j = tid; j < 260; j += 256) {
        float y0 = sy[j], y1 = sy[j + 1], y2 = sy[j + 2], y3 = sy[j + 3], y4 = sy[j + 4];
        uint32_t addr = sh_base + j * 80;
#pragma unroll 4
        for (int cq = 0; cq < 16; cq++) {
            float a[4];
#pragma unroll
            for (int q = 0; q < 4; q++) {
                int c = cq * 4 + q;
                a[q] = sb1[c] + y0 * sw1[c] + y1 * sw1[64 + c] + y2 * sw1[128 + c]
                              + y3 * sw1[192 + c] + y4 * sw1[256 + c];
            }
            unsigned short lo = tanh2_e4m3(a[0], a[1]);
            unsigned short hi = tanh2_e4m3(a[2], a[3]);
            uint32_t u;
            asm("mov.b32 %0, {%1,%2};" : "=r"(u) : "h"(lo), "h"(hi));
            sts32(addr + cq * 4, u);
        }
    }
    __syncthreads();

    // ---- phase 2: conv2 fp8 MMA (M=256, N=64, K=320), warp w owns 32 rows ----
    int m0 = w * 32;
    float acc[2][8][4];
#pragma unroll
    for (int nb = 0; nb < 8; nb++) {
        float b0v = sb2[nb * 8 + tg * 2], b1v = sb2[nb * 8 + tg * 2 + 1];
#pragma unroll
        for (int mt = 0; mt < 2; mt++) {
            acc[mt][nb][0] = b0v; acc[mt][nb][1] = b1v;
            acc[mt][nb][2] = b0v; acc[mt][nb][3] = b1v;
        }
    }
#pragma unroll 5
    for (int kb = 0; kb < 10; kb++) {
        int kshift = kb >> 1;
        uint32_t off = (uint32_t)((kb & 1) * 32 + ((lane >> 4) << 4));
        uint32_t a[2][4];
#pragma unroll
        for (int mt = 0; mt < 2; mt++) {
            uint32_t r = (uint32_t)(m0 + mt * 16 + (lane & 15) + kshift);
            ldmatrix_x4(a[mt], sh_base + r * 80 + off);
        }
#pragma unroll
        for (int nb = 0; nb < 8; nb++) {
            uint2 b = *reinterpret_cast<const uint2*>(
                smem + OFF_W2F + (size_t)(((kb << 3) + nb) * 32 + lane) * 8);
            mma_fp8(acc[0][nb], a[0], b.x, b.y);
            mma_fp8(acc[1][nb], a[1], b.x, b.y);
        }
    }

    // ---- phase 3: tanh epilogue -> sH2 (overlays sH1, same layout) ----
    unsigned short h2e[2][8][2];
#pragma unroll
    for (int mt = 0; mt < 2; mt++)
#pragma unroll
        for (int nb = 0; nb < 8; nb++) {
            h2e[mt][nb][0] = tanh2_e4m3(acc[mt][nb][0], acc[mt][nb][1]);
            h2e[mt][nb][1] = tanh2_e4m3(acc[mt][nb][2], acc[mt][nb][3]);
        }
    __syncthreads();   // all warps done reading sH1
#pragma unroll
    for (int mt = 0; mt < 2; mt++) {
        uint32_t r0 = (uint32_t)(m0 + mt * 16 + gg);
#pragma unroll
        for (int nb = 0; nb < 8; nb++) {
            uint32_t cb = (uint32_t)(nb * 8 + tg * 2);
            sts16(sh_base + r0 * 80 + cb, h2e[mt][nb][0]);
            sts16(sh_base + (r0 + 8) * 80 + cb, h2e[mt][nb][1]);
        }
    }
    __syncthreads();

    // ---- phase 4: conv3 fp8 MMA (M=256, N=8pad, K=320) -> coeffs ----
    float acc3[2][4];
    {
        float bz0 = (tg < 2) ? sb3[tg * 2] : 0.0f;
        float bz1 = (tg < 2) ? sb3[tg * 2 + 1] : 0.0f;
#pragma unroll
        for (int mt = 0; mt < 2; mt++) {
            acc3[mt][0] = bz0; acc3[mt][1] = bz1; acc3[mt][2] = bz0; acc3[mt][3] = bz1;
        }
    }
#pragma unroll 5
    for (int kb = 0; kb < 10; kb++) {
        int kshift = kb >> 1;
        uint32_t off = (uint32_t)((kb & 1) * 32 + ((lane >> 4) << 4));
        uint32_t a[2][4];
#pragma unroll
        for (int mt = 0; mt < 2; mt++) {
            uint32_t r = (uint32_t)(m0 + mt * 16 + (lane & 15) + kshift);
            ldmatrix_x4(a[mt], sh_base + r * 80 + off);
        }
        uint2 b = *reinterpret_cast<const uint2*>(
            smem + OFF_W3F + (size_t)((kb << 5) + lane) * 8);
        mma_fp8(acc3[0], a[0], b.x, b.y);
        mma_fp8(acc3[1], a[1], b.x, b.y);
    }
    if (tg < 2) {
#pragma unroll
        for (int mt = 0; mt < 2; mt++) {
            int p = m0 + mt * 16 + gg;
            int c0 = tg * 2;
            scoef[p * 4 + c0]           = acc3[mt][0];
            scoef[p * 4 + c0 + 1]       = acc3[mt][1];
            scoef[(p + 8) * 4 + c0]     = acc3[mt][2];
            scoef[(p + 8) * 4 + c0 + 1] = acc3[mt][3];
        }
    }
    __syncthreads();

    // ---- phase 5: alpha -> grad -> TVD flux -> update ----
    if (tid < 252) {   // grad at position t0-2+tid
        float4 c = *reinterpret_cast<const float4*>(scoef + tid * 4);
        float S = c.x + c.y + c.z + c.w;
        const float NB0 = -0.44721359549995793f;
        const float NBD = -0.13819660112501052f;
        float a0 = (float)( 1.0 / 12.0) + NB0 * S;
        float a1 = (float)(-2.0 / 3.0)  + c.x + NBD * S;
        float a2 =                        c.y + NBD * S;
        float a3 = (float)( 2.0 / 3.0)  + c.z + NBD * S;
        float a4 = (float)(-1.0 / 12.0) + c.w + NBD * S;
        float g = sPrim[tid + 4] * a0 + sPrim[tid + 5] * a1 + sPrim[tid + 6] * a2
                + sPrim[tid + 7] * a3 + sPrim[tid + 8] * a4;
        sg[tid] = g * 64.0f;
    }
    __syncthreads();
    if (tid < 250) {   // flux at position t0-1+tid
        float gm1 = sg[tid], g0 = sg[tid + 1], g1 = sg[tid + 2];
        float aa0 = (g0 < 0.0f) ? -1.0f : 1.0f;
        float ri0 = gm1 / (fmaxf(fabsf(g0), 1e-15f) * aa0);
        float phi0 = (ri0 * ri0 + ri0) / (ri0 * ri0 + 1.0f);
        float aa1 = (g1 < 0.0f) ? -1.0f : 1.0f;
        float ri1 = g0 / (fmaxf(fabsf(g1), 1e-15f) * aa1);
        float phi1 = (ri1 * ri1 + ri1) / (ri1 * ri1 + 1.0f);
        float uL = sPrim[tid + 7] + 0.0078125f * phi0 * g0;
        float uR = sPrim[tid + 8] - 0.0078125f * phi1 * g1;
        sf[tid] = 0.25f * (uL * uL + uR * uR) - 0.25f * fabsf(uL + uR) * (uR - uL);
    }
    __syncthreads();
    if (tid < OUT_TILE) {
        int o = t0 + tid;
        if (o < LROW)
            out[rb + o] = sPrim[tid + 8] - 0.01f * (sf[tid + 1] - sf[tid]);
    }
}

// ---------------- launch ----------------
extern "C" void kernel_launch(void* const* d_in, const int* in_sizes, int n_in,
                              void* d_out, int out_size) {
    const float* Prim = (const float*)d_in[0];
    const float* W1   = (const float*)d_in[1];
    const float* b1   = (const float*)d_in[2];
    const float* W2   = (const float*)d_in[3];
    const float* b2   = (const float*)d_in[4];
    const float* W3   = (const float*)d_in[5];
    const float* b3   = (const float*)d_in[6];
    float* out = (float*)d_out;

    cudaFuncSetAttribute(k_mega, cudaFuncAttributeMaxDynamicSharedMemorySize, SMEM_TOTAL);

    k_stats<<<NROWS, 256>>>(Prim);
    k_prep<<<24, 256>>>(W2, W3);
    k_mega<<<dim3(NTILES, NROWS), 256, SMEM_TOTAL>>>(Prim, W1, b1, b2, b3, out);
}